// round 1
// baseline (speedup 1.0000x reference)
#include <cuda_runtime.h>
#include <math.h>

#define Bdim 2
#define Sdim 2048
#define Edim 1024
#define Hdim 16
#define HDdim 64
#define RDdim 32
#define MPdim 8
#define LOCAL 128          // HD*H/MP
#define MROWS (Bdim*Sdim)  // 4096

// Scratch (allocation-free per harness rules)
__device__ float g_qkv[Bdim*Sdim*3*Edim];      // 50.3 MB
__device__ float g_q[Bdim*Hdim*Sdim*HDdim];    // 16.8 MB
__device__ float g_k[Bdim*Hdim*Sdim*HDdim];
__device__ float g_v[Bdim*Hdim*Sdim*HDdim];
__device__ float g_ctx[Bdim*Sdim*Edim];        // 16.8 MB, [b,s,h,d]

// ---------------------------------------------------------------------------
// SGEMM: C[M,N] = A[M,K] @ W[N,K]^T   (row-major everywhere)
// BM=128, BN=64, BK=16, 256 threads, 8x4 microtile
// ---------------------------------------------------------------------------
__global__ __launch_bounds__(256) void sgemm_nt(
    const float* __restrict__ A, const float* __restrict__ Wt,
    float* __restrict__ C, int M, int N, int K)
{
    constexpr int BM = 128, BN = 64, BK = 16, TM = 8, TN = 4;
    __shared__ float As[BM][BK];
    __shared__ float Bs[BK][BN + 1];

    const int tid = threadIdx.x;
    const int tx = tid & 15;        // 16 cols of threads
    const int ty = tid >> 4;        // 16 rows of threads
    const int m0 = blockIdx.y * BM;
    const int n0 = blockIdx.x * BN;

    float acc[TM][TN];
#pragma unroll
    for (int i = 0; i < TM; i++)
#pragma unroll
        for (int j = 0; j < TN; j++) acc[i][j] = 0.0f;

    for (int k0 = 0; k0 < K; k0 += BK) {
        // load A tile (128x16): 8 elems/thread, kk contiguous
#pragma unroll
        for (int it = 0; it < (BM * BK) / 256; it++) {
            int i = tid + it * 256;
            int mm = i >> 4, kk = i & 15;
            As[mm][kk] = A[(size_t)(m0 + mm) * K + k0 + kk];
        }
        // load W^T tile (16x64): Bs[kk][nn] = Wt[(n0+nn)*K + k0+kk]
#pragma unroll
        for (int it = 0; it < (BK * BN) / 256; it++) {
            int i = tid + it * 256;
            int nn = i >> 4, kk = i & 15;
            Bs[kk][nn] = Wt[(size_t)(n0 + nn) * K + k0 + kk];
        }
        __syncthreads();

#pragma unroll
        for (int kk = 0; kk < BK; kk++) {
            float ra[TM], rb[TN];
#pragma unroll
            for (int i = 0; i < TM; i++) ra[i] = As[ty * TM + i][kk];
#pragma unroll
            for (int j = 0; j < TN; j++) rb[j] = Bs[kk][tx * TN + j];
#pragma unroll
            for (int i = 0; i < TM; i++)
#pragma unroll
                for (int j = 0; j < TN; j++) acc[i][j] += ra[i] * rb[j];
        }
        __syncthreads();
    }

#pragma unroll
    for (int i = 0; i < TM; i++) {
        int m = m0 + ty * TM + i;
#pragma unroll
        for (int j = 0; j < TN; j++) {
            C[(size_t)m * N + n0 + tx * TN + j] = acc[i][j];
        }
    }
}

// ---------------------------------------------------------------------------
// QKV de-interleave + RoPE.  Reference split order is q, v, k!
// qkv[b,s, mp*384 + {0,128,256} + r*64 + d] with h = mp*2 + r
// Writes [b,h,s,d] layout for flash kernel.
// ---------------------------------------------------------------------------
__global__ __launch_bounds__(256) void qkv_transform(const float* __restrict__ qkv)
{
    int idx = blockIdx.x * blockDim.x + threadIdx.x;
    if (idx >= Bdim * Sdim * Hdim * HDdim) return;
    int d = idx & (HDdim - 1);
    int h = (idx >> 6) & (Hdim - 1);
    int s = (idx >> 10) & (Sdim - 1);
    int b = idx >> 21;

    int mp = h >> 1, r = h & 1;
    const float* base = qkv + (size_t)(b * Sdim + s) * (3 * Edim) + mp * (3 * LOCAL) + r * HDdim;

    float qv = base[d];
    float vv = base[LOCAL + d];
    float kv = base[2 * LOCAL + d];

    if (d < RDdim) {
        int i = d >> 1;
        // inv_freq = 10000^{-(2i)/RD}
        float inv = powf(10000.0f, -(float)(2 * i) / (float)RDdim);
        float ang = (float)s * inv;
        float sn, cs;
        sincosf(ang, &sn, &cs);
        int partner = d ^ 1;
        float qp = base[partner];
        float kp = base[2 * LOCAL + partner];
        if ((d & 1) == 0) {     // even: x*cos - x_{+1}*sin
            qv = qv * cs - qp * sn;
            kv = kv * cs - kp * sn;
        } else {                // odd:  x*cos + x_{-1}*sin
            qv = qv * cs + qp * sn;
            kv = kv * cs + kp * sn;
        }
    }
    size_t o = (size_t)((b * Hdim + h) * Sdim + s) * HDdim + d;
    g_q[o] = qv;
    g_k[o] = kv;
    g_v[o] = vv;
}

// ---------------------------------------------------------------------------
// Flash attention, causal. 64 query rows x 64 key cols per tile.
// grid = (S/64, B*H), 256 threads (16x16, each thread 4x4).
// Writes ctx in [b,s,h,d] so the output GEMM reads it contiguously.
// ---------------------------------------------------------------------------
__global__ __launch_bounds__(256) void flash_attn_kernel()
{
    extern __shared__ float sm[];
    float* Qs  = sm;                 // [64][64]
    float* Kts = Qs + 64 * 64;       // [64][65]  K transposed: Kts[d][key]
    float* Vs  = Kts + 64 * 65;      // [64][64]  Vs[key][d]
    float* Ps  = Vs + 64 * 64;       // [64][65]

    const int qt = blockIdx.x;
    const int bh = blockIdx.y;
    const float* Qbase = g_q + (size_t)bh * Sdim * HDdim;
    const float* Kbase = g_k + (size_t)bh * Sdim * HDdim;
    const float* Vbase = g_v + (size_t)bh * Sdim * HDdim;

    const int tid = threadIdx.x;
    const int tx = tid & 15;
    const int ty = tid >> 4;

    // load Q tile
    for (int i = tid; i < 64 * 64; i += 256) {
        int r = i >> 6, c = i & 63;
        Qs[r * 64 + c] = Qbase[(size_t)(qt * 64 + r) * HDdim + c];
    }

    float m_i[4], l_i[4], acc[4][4];
#pragma unroll
    for (int i = 0; i < 4; i++) {
        m_i[i] = -1e30f;
        l_i[i] = 0.0f;
#pragma unroll
        for (int j = 0; j < 4; j++) acc[i][j] = 0.0f;
    }
    const float scale = 0.125f;   // 1/sqrt(64)

    for (int kt = 0; kt <= qt; kt++) {
        __syncthreads();  // previous iter done with Kts/Vs/Ps; also fences Q load
        for (int i = tid; i < 64 * 64; i += 256) {
            int r = i >> 6, c = i & 63;   // r = key index, c = d
            float kvv = Kbase[(size_t)(kt * 64 + r) * HDdim + c];
            Kts[c * 65 + r] = kvv;
            Vs[r * 64 + c] = Vbase[(size_t)(kt * 64 + r) * HDdim + c];
        }
        __syncthreads();

        // S = scale * Q @ K^T
        float sv[4][4];
#pragma unroll
        for (int i = 0; i < 4; i++)
#pragma unroll
            for (int j = 0; j < 4; j++) sv[i][j] = 0.0f;

#pragma unroll 8
        for (int kk = 0; kk < 64; kk++) {
            float ra[4], rb[4];
#pragma unroll
            for (int i = 0; i < 4; i++) ra[i] = Qs[(ty * 4 + i) * 64 + kk];
#pragma unroll
            for (int j = 0; j < 4; j++) rb[j] = Kts[kk * 65 + tx * 4 + j];
#pragma unroll
            for (int i = 0; i < 4; i++)
#pragma unroll
                for (int j = 0; j < 4; j++) sv[i][j] += ra[i] * rb[j];
        }

        const int qrow0 = qt * 64 + ty * 4;
        const int kcol0 = kt * 64 + tx * 4;
#pragma unroll
        for (int i = 0; i < 4; i++)
#pragma unroll
            for (int j = 0; j < 4; j++) {
                sv[i][j] *= scale;
                if (kcol0 + j > qrow0 + i) sv[i][j] = -1e9f;  // matches reference mask
            }

        // online softmax update
#pragma unroll
        for (int i = 0; i < 4; i++) {
            float mx = sv[i][0];
#pragma unroll
            for (int j = 1; j < 4; j++) mx = fmaxf(mx, sv[i][j]);
#pragma unroll
            for (int off = 8; off >= 1; off >>= 1)
                mx = fmaxf(mx, __shfl_xor_sync(0xffffffffu, mx, off, 16));
            float mn = fmaxf(m_i[i], mx);
            float alpha = __expf(m_i[i] - mn);
            float rs = 0.0f;
#pragma unroll
            for (int j = 0; j < 4; j++) {
                float p = __expf(sv[i][j] - mn);
                sv[i][j] = p;
                rs += p;
            }
#pragma unroll
            for (int off = 8; off >= 1; off >>= 1)
                rs += __shfl_xor_sync(0xffffffffu, rs, off, 16);
            l_i[i] = l_i[i] * alpha + rs;
            m_i[i] = mn;
#pragma unroll
            for (int j = 0; j < 4; j++) acc[i][j] *= alpha;
        }

        // stage P, then O += P @ V
#pragma unroll
        for (int i = 0; i < 4; i++)
#pragma unroll
            for (int j = 0; j < 4; j++)
                Ps[(ty * 4 + i) * 65 + tx * 4 + j] = sv[i][j];
        __syncthreads();

#pragma unroll 8
        for (int kk = 0; kk < 64; kk++) {
            float rp[4], rv[4];
#pragma unroll
            for (int i = 0; i < 4; i++) rp[i] = Ps[(ty * 4 + i) * 65 + kk];
#pragma unroll
            for (int j = 0; j < 4; j++) rv[j] = Vs[kk * 64 + tx * 4 + j];
#pragma unroll
            for (int i = 0; i < 4; i++)
#pragma unroll
                for (int j = 0; j < 4; j++) acc[i][j] += rp[i] * rv[j];
        }
    }

    // write context in [b, s, h, d]
    const int b = bh >> 4;      // bh / H
    const int h = bh & 15;      // bh % H
#pragma unroll
    for (int i = 0; i < 4; i++) {
        int srow = qt * 64 + ty * 4 + i;
        float inv_l = 1.0f / l_i[i];
#pragma unroll
        for (int j = 0; j < 4; j++) {
            g_ctx[(size_t)((b * Sdim + srow) * Hdim + h) * HDdim + tx * 4 + j] = acc[i][j] * inv_l;
        }
    }
}

// ---------------------------------------------------------------------------
extern "C" void kernel_launch(void* const* d_in, const int* in_sizes, int n_in,
                              void* d_out, int out_size)
{
    const float* hs    = (const float*)d_in[0];   // [B,S,E]
    const float* w_qkv = (const float*)d_in[1];   // [3E,E]
    const float* w_out = (const float*)d_in[2];   // [E,E]
    float* out = (float*)d_out;                   // [B,S,E]

    float *p_qkv, *p_ctx;
    cudaGetSymbolAddress((void**)&p_qkv, g_qkv);
    cudaGetSymbolAddress((void**)&p_ctx, g_ctx);

    // 1) QKV projection: [4096,1024] @ [3072,1024]^T -> [4096,3072]
    {
        dim3 grid(3 * Edim / 64, MROWS / 128);
        sgemm_nt<<<grid, 256>>>(hs, w_qkv, p_qkv, MROWS, 3 * Edim, Edim);
    }

    // 2) split + RoPE
    {
        int total = Bdim * Sdim * Hdim * HDdim;
        qkv_transform<<<(total + 255) / 256, 256>>>(p_qkv);
    }

    // 3) flash attention
    {
        const int smem = (64 * 64 + 64 * 65 + 64 * 64 + 64 * 65) * sizeof(float); // 66048
        cudaFuncSetAttribute(flash_attn_kernel,
                             cudaFuncAttributeMaxDynamicSharedMemorySize, smem);
        dim3 grid(Sdim / 64, Bdim * Hdim);
        flash_attn_kernel<<<grid, 256, smem>>>();
    }

    // 4) output projection: [4096,1024] @ [1024,1024]^T -> [4096,1024]
    {
        dim3 grid(Edim / 64, MROWS / 128);
        sgemm_nt<<<grid, 256>>>(p_ctx, w_out, out, MROWS, Edim, Edim);
    }
}

// round 3
// speedup vs baseline: 5.4103x; 5.4103x over previous
#include <cuda_runtime.h>
#include <math.h>
#include <stdint.h>

#define Bdim 2
#define Sdim 2048
#define Edim 1024
#define Hdim 16
#define HDdim 64
#define RDdim 32
#define LOCAL 128          // HD*H/MP
#define MROWS (Bdim*Sdim)  // 4096

// Scratch (allocation-free per harness rules)
__device__ float g_qkv[Bdim*Sdim*3*Edim];
__device__ float g_q[Bdim*Hdim*Sdim*HDdim];
__device__ float g_k[Bdim*Hdim*Sdim*HDdim];
__device__ float g_v[Bdim*Hdim*Sdim*HDdim];
__device__ float g_ctx[Bdim*Sdim*Edim];        // [b,s,h,d]

__device__ __forceinline__ float to_tf32(float x) {
    uint32_t u;
    asm("cvt.rna.tf32.f32 %0, %1;" : "=r"(u) : "f"(x));
    return __uint_as_float(u);
}
__device__ __forceinline__ uint32_t f2u(float x) { return __float_as_uint(x); }

__device__ __forceinline__ void mma_tf32(float c[4],
    uint32_t a0, uint32_t a1, uint32_t a2, uint32_t a3,
    uint32_t b0, uint32_t b1)
{
    asm volatile(
        "mma.sync.aligned.m16n8k8.row.col.f32.tf32.tf32.f32 "
        "{%0,%1,%2,%3}, {%4,%5,%6,%7}, {%8,%9}, {%0,%1,%2,%3};"
        : "+f"(c[0]), "+f"(c[1]), "+f"(c[2]), "+f"(c[3])
        : "r"(a0), "r"(a1), "r"(a2), "r"(a3), "r"(b0), "r"(b1));
}

// ---------------------------------------------------------------------------
// TF32 tensor-core GEMM: C[M,N] = A[M,K] @ W[N,K]^T  (row-major)
// BM=128, BN=128, BK=32, 256 threads (8 warps, 4x2), warp tile 32x64.
// ---------------------------------------------------------------------------
__global__ __launch_bounds__(256) void sgemm_tf32(
    const float* __restrict__ A, const float* __restrict__ W,
    float* __restrict__ C, int M, int N, int K)
{
    constexpr int AST = 36;                 // 36%32==4 -> conflict-free frag loads
    __shared__ float As[128 * AST];
    __shared__ float Ws[128 * AST];

    const int tid  = threadIdx.x;
    const int lane = tid & 31, wid = tid >> 5;
    const int gid  = lane >> 2, tig = lane & 3;
    const int wm   = (wid & 3) * 32;
    const int wn   = (wid >> 2) * 64;
    const int m0   = blockIdx.y * 128;
    const int n0   = blockIdx.x * 128;

    float c[2][8][4];
#pragma unroll
    for (int mi = 0; mi < 2; mi++)
#pragma unroll
        for (int ni = 0; ni < 8; ni++)
#pragma unroll
            for (int j = 0; j < 4; j++) c[mi][ni][j] = 0.0f;

    for (int k0 = 0; k0 < K; k0 += 32) {
#pragma unroll
        for (int it = 0; it < 4; it++) {
            int idx = tid + it * 256;
            int r = idx >> 3, c4 = idx & 7;
            float4 va = *(const float4*)(A + (size_t)(m0 + r) * K + k0 + c4 * 4);
            float* da = As + r * AST + c4 * 4;
            da[0] = to_tf32(va.x); da[1] = to_tf32(va.y);
            da[2] = to_tf32(va.z); da[3] = to_tf32(va.w);
            float4 vw = *(const float4*)(W + (size_t)(n0 + r) * K + k0 + c4 * 4);
            float* dw = Ws + r * AST + c4 * 4;
            dw[0] = to_tf32(vw.x); dw[1] = to_tf32(vw.y);
            dw[2] = to_tf32(vw.z); dw[3] = to_tf32(vw.w);
        }
        __syncthreads();

#pragma unroll
        for (int kk = 0; kk < 4; kk++) {
            const int kb = kk * 8;
            uint32_t a[2][4];
#pragma unroll
            for (int mi = 0; mi < 2; mi++) {
                int rb = wm + mi * 16;
                a[mi][0] = f2u(As[(rb + gid    ) * AST + kb + tig    ]);
                a[mi][1] = f2u(As[(rb + gid + 8) * AST + kb + tig    ]);
                a[mi][2] = f2u(As[(rb + gid    ) * AST + kb + tig + 4]);
                a[mi][3] = f2u(As[(rb + gid + 8) * AST + kb + tig + 4]);
            }
#pragma unroll
            for (int ni = 0; ni < 8; ni++) {
                uint32_t b0 = f2u(Ws[(wn + ni * 8 + gid) * AST + kb + tig    ]);
                uint32_t b1 = f2u(Ws[(wn + ni * 8 + gid) * AST + kb + tig + 4]);
                mma_tf32(c[0][ni], a[0][0], a[0][1], a[0][2], a[0][3], b0, b1);
                mma_tf32(c[1][ni], a[1][0], a[1][1], a[1][2], a[1][3], b0, b1);
            }
        }
        __syncthreads();
    }

#pragma unroll
    for (int mi = 0; mi < 2; mi++) {
#pragma unroll
        for (int ni = 0; ni < 8; ni++) {
            int r  = m0 + wm + mi * 16 + gid;
            int cc = n0 + wn + ni * 8 + 2 * tig;
            float2 v01 = make_float2(c[mi][ni][0], c[mi][ni][1]);
            float2 v23 = make_float2(c[mi][ni][2], c[mi][ni][3]);
            *(float2*)(C + (size_t)r * N + cc)       = v01;
            *(float2*)(C + (size_t)(r + 8) * N + cc) = v23;
        }
    }
}

// ---------------------------------------------------------------------------
// QKV de-interleave + RoPE (reference split order is q, v, k)
// ---------------------------------------------------------------------------
__global__ __launch_bounds__(256) void qkv_transform(const float* __restrict__ qkv)
{
    int idx = blockIdx.x * blockDim.x + threadIdx.x;
    if (idx >= Bdim * Sdim * Hdim * HDdim) return;
    int d = idx & (HDdim - 1);
    int h = (idx >> 6) & (Hdim - 1);
    int s = (idx >> 10) & (Sdim - 1);
    int b = idx >> 21;

    int mp = h >> 1, r = h & 1;
    const float* base = qkv + (size_t)(b * Sdim + s) * (3 * Edim) + mp * (3 * LOCAL) + r * HDdim;

    float qv = base[d];
    float vv = base[LOCAL + d];
    float kv = base[2 * LOCAL + d];

    if (d < RDdim) {
        int i = d >> 1;
        float inv = powf(10000.0f, -(float)(2 * i) / (float)RDdim);
        float ang = (float)s * inv;
        float sn, cs;
        sincosf(ang, &sn, &cs);
        int partner = d ^ 1;
        float qp = base[partner];
        float kp = base[2 * LOCAL + partner];
        if ((d & 1) == 0) {
            qv = qv * cs - qp * sn;
            kv = kv * cs - kp * sn;
        } else {
            qv = qv * cs + qp * sn;
            kv = kv * cs + kp * sn;
        }
    }
    size_t o = (size_t)((b * Hdim + h) * Sdim + s) * HDdim + d;
    g_q[o] = qv;
    g_k[o] = kv;
    g_v[o] = vv;
}

// ---------------------------------------------------------------------------
// Flash attention with tf32 mma. 128 threads (4 warps), 64-query blocks,
// 64-key tiles. Q fragments register-resident. P staging buffer ALIASES the
// K tile (K is dead after S=Q@K^T; a __syncthreads separates the phases).
// Static smem: Ks[64*68] + Vs[64*68] = 34816 B (no func-attr call needed).
// ---------------------------------------------------------------------------
#define KST 68
__global__ __launch_bounds__(128) void flash_mma()
{
    __shared__ float Ks[64 * KST];   // doubles as P staging (per-warp strips)
    __shared__ float Vs[64 * KST];

    const int qt = blockIdx.x;
    const int bh = blockIdx.y;
    const int tid = threadIdx.x;
    const int lane = tid & 31, w = tid >> 5;
    const int gid = lane >> 2, tig = lane & 3;

    const float* Qb = g_q + ((size_t)bh * Sdim + qt * 64) * HDdim;
    const float* Kh = g_k + (size_t)bh * Sdim * HDdim;
    const float* Vh = g_v + (size_t)bh * Sdim * HDdim;

    // stage this warp's 16 Q rows in its Ks strip, extract A fragments
    float* Pw = Ks + w * 16 * KST;
#pragma unroll
    for (int it = 0; it < 8; it++) {
        int idx = lane + it * 32;          // 256 float4 per warp
        int r = idx >> 4, c4 = idx & 15;
        float4 v = *(const float4*)(Qb + (size_t)(w * 16 + r) * HDdim + c4 * 4);
        float* dst = Pw + r * KST + c4 * 4;
        dst[0] = to_tf32(v.x); dst[1] = to_tf32(v.y);
        dst[2] = to_tf32(v.z); dst[3] = to_tf32(v.w);
    }
    __syncwarp();
    uint32_t qa[8][4];
#pragma unroll
    for (int kk = 0; kk < 8; kk++) {
        int kb = kk * 8;
        qa[kk][0] = f2u(Pw[(gid    ) * KST + kb + tig    ]);
        qa[kk][1] = f2u(Pw[(gid + 8) * KST + kb + tig    ]);
        qa[kk][2] = f2u(Pw[(gid    ) * KST + kb + tig + 4]);
        qa[kk][3] = f2u(Pw[(gid + 8) * KST + kb + tig + 4]);
    }

    float m0r = -1e30f, m1r = -1e30f, l0 = 0.0f, l1 = 0.0f;
    float o[8][4];
#pragma unroll
    for (int ni = 0; ni < 8; ni++)
#pragma unroll
        for (int j = 0; j < 4; j++) o[ni][j] = 0.0f;

    const float scale = 0.125f;   // 1/sqrt(64)

    for (int kt = 0; kt <= qt; kt++) {
        __syncthreads();   // prev iter done reading Ks(=P) and Vs; Q frags extracted
        const float* Kb = Kh + (size_t)(kt * 64) * HDdim;
        const float* Vb = Vh + (size_t)(kt * 64) * HDdim;
#pragma unroll
        for (int it = 0; it < 8; it++) {
            int idx = tid + it * 128;
            int r = idx >> 4, c4 = idx & 15;
            float4 kv = *(const float4*)(Kb + (size_t)r * HDdim + c4 * 4);
            float* dk = Ks + r * KST + c4 * 4;
            dk[0] = to_tf32(kv.x); dk[1] = to_tf32(kv.y);
            dk[2] = to_tf32(kv.z); dk[3] = to_tf32(kv.w);
            float4 vv = *(const float4*)(Vb + (size_t)r * HDdim + c4 * 4);
            float* dv = Vs + r * KST + c4 * 4;
            dv[0] = to_tf32(vv.x); dv[1] = to_tf32(vv.y);
            dv[2] = to_tf32(vv.z); dv[3] = to_tf32(vv.w);
        }
        __syncthreads();

        // S = Q @ K^T
        float s[8][4];
#pragma unroll
        for (int ni = 0; ni < 8; ni++)
#pragma unroll
            for (int j = 0; j < 4; j++) s[ni][j] = 0.0f;

#pragma unroll
        for (int kk = 0; kk < 8; kk++) {
            int kb = kk * 8;
#pragma unroll
            for (int ni = 0; ni < 8; ni++) {
                uint32_t b0 = f2u(Ks[(ni * 8 + gid) * KST + kb + tig    ]);
                uint32_t b1 = f2u(Ks[(ni * 8 + gid) * KST + kb + tig + 4]);
                mma_tf32(s[ni], qa[kk][0], qa[kk][1], qa[kk][2], qa[kk][3], b0, b1);
            }
        }

        // scale + causal mask (only diagonal tile)
        if (kt == qt) {
#pragma unroll
            for (int ni = 0; ni < 8; ni++)
#pragma unroll
                for (int j = 0; j < 4; j++) {
                    int col  = ni * 8 + 2 * tig + (j & 1);
                    int rowl = w * 16 + gid + ((j >= 2) ? 8 : 0);
                    s[ni][j] = (col > rowl) ? -1e9f : s[ni][j] * scale;
                }
        } else {
#pragma unroll
            for (int ni = 0; ni < 8; ni++)
#pragma unroll
                for (int j = 0; j < 4; j++) s[ni][j] *= scale;
        }

        // online softmax: thread owns rows (gid, gid+8)
        float mx0 = -1e30f, mx1 = -1e30f;
#pragma unroll
        for (int ni = 0; ni < 8; ni++) {
            mx0 = fmaxf(mx0, fmaxf(s[ni][0], s[ni][1]));
            mx1 = fmaxf(mx1, fmaxf(s[ni][2], s[ni][3]));
        }
        mx0 = fmaxf(mx0, __shfl_xor_sync(0xffffffffu, mx0, 1));
        mx0 = fmaxf(mx0, __shfl_xor_sync(0xffffffffu, mx0, 2));
        mx1 = fmaxf(mx1, __shfl_xor_sync(0xffffffffu, mx1, 1));
        mx1 = fmaxf(mx1, __shfl_xor_sync(0xffffffffu, mx1, 2));

        float mn0 = fmaxf(m0r, mx0), mn1 = fmaxf(m1r, mx1);
        float al0 = __expf(m0r - mn0), al1 = __expf(m1r - mn1);
        float rs0 = 0.0f, rs1 = 0.0f;
#pragma unroll
        for (int ni = 0; ni < 8; ni++) {
            float p0 = __expf(s[ni][0] - mn0); s[ni][0] = p0; rs0 += p0;
            float p1 = __expf(s[ni][1] - mn0); s[ni][1] = p1; rs0 += p1;
            float p2 = __expf(s[ni][2] - mn1); s[ni][2] = p2; rs1 += p2;
            float p3 = __expf(s[ni][3] - mn1); s[ni][3] = p3; rs1 += p3;
        }
        rs0 += __shfl_xor_sync(0xffffffffu, rs0, 1);
        rs0 += __shfl_xor_sync(0xffffffffu, rs0, 2);
        rs1 += __shfl_xor_sync(0xffffffffu, rs1, 1);
        rs1 += __shfl_xor_sync(0xffffffffu, rs1, 2);

        l0 = l0 * al0 + rs0;  l1 = l1 * al1 + rs1;
        m0r = mn0;  m1r = mn1;
#pragma unroll
        for (int ni = 0; ni < 8; ni++) {
            o[ni][0] *= al0; o[ni][1] *= al0;
            o[ni][2] *= al1; o[ni][3] *= al1;
        }

        // all warps done reading Ks before P overwrites it
        __syncthreads();
#pragma unroll
        for (int ni = 0; ni < 8; ni++) {
            int cb = ni * 8 + 2 * tig;
            Pw[(gid    ) * KST + cb    ] = to_tf32(s[ni][0]);
            Pw[(gid    ) * KST + cb + 1] = to_tf32(s[ni][1]);
            Pw[(gid + 8) * KST + cb    ] = to_tf32(s[ni][2]);
            Pw[(gid + 8) * KST + cb + 1] = to_tf32(s[ni][3]);
        }
        __syncwarp();

        // O += P @ V  (P is warp-private strip; V read-only)
#pragma unroll
        for (int kk = 0; kk < 8; kk++) {
            int kb = kk * 8;
            uint32_t pa0 = f2u(Pw[(gid    ) * KST + kb + tig    ]);
            uint32_t pa1 = f2u(Pw[(gid + 8) * KST + kb + tig    ]);
            uint32_t pa2 = f2u(Pw[(gid    ) * KST + kb + tig + 4]);
            uint32_t pa3 = f2u(Pw[(gid + 8) * KST + kb + tig + 4]);
#pragma unroll
            for (int ni = 0; ni < 8; ni++) {
                uint32_t b0 = f2u(Vs[(kb + tig    ) * KST + ni * 8 + gid]);
                uint32_t b1 = f2u(Vs[(kb + tig + 4) * KST + ni * 8 + gid]);
                mma_tf32(o[ni], pa0, pa1, pa2, pa3, b0, b1);
            }
        }
    }

    // epilogue -> g_ctx[b, s, h, d]
    const int b = bh >> 4, h = bh & 15;
    const float inv0 = 1.0f / l0, inv1 = 1.0f / l1;
    const int row0 = qt * 64 + w * 16 + gid;
#pragma unroll
    for (int ni = 0; ni < 8; ni++) {
        int d0 = ni * 8 + 2 * tig;
        float2 v01 = make_float2(o[ni][0] * inv0, o[ni][1] * inv0);
        float2 v23 = make_float2(o[ni][2] * inv1, o[ni][3] * inv1);
        *(float2*)(g_ctx + (size_t)((b * Sdim + row0    ) * Hdim + h) * HDdim + d0) = v01;
        *(float2*)(g_ctx + (size_t)((b * Sdim + row0 + 8) * Hdim + h) * HDdim + d0) = v23;
    }
}

// ---------------------------------------------------------------------------
extern "C" void kernel_launch(void* const* d_in, const int* in_sizes, int n_in,
                              void* d_out, int out_size)
{
    const float* hs    = (const float*)d_in[0];   // [B,S,E]
    const float* w_qkv = (const float*)d_in[1];   // [3E,E]
    const float* w_out = (const float*)d_in[2];   // [E,E]
    float* out = (float*)d_out;                   // [B,S,E]

    float *p_qkv, *p_ctx;
    cudaGetSymbolAddress((void**)&p_qkv, g_qkv);
    cudaGetSymbolAddress((void**)&p_ctx, g_ctx);

    // 1) QKV projection: [4096,1024] @ [3072,1024]^T
    {
        dim3 grid(3 * Edim / 128, MROWS / 128);
        sgemm_tf32<<<grid, 256>>>(hs, w_qkv, p_qkv, MROWS, 3 * Edim, Edim);
    }
    // 2) split + RoPE
    {
        int total = Bdim * Sdim * Hdim * HDdim;
        qkv_transform<<<(total + 255) / 256, 256>>>(p_qkv);
    }
    // 3) flash attention (tf32 mma, static smem)
    {
        dim3 grid(Sdim / 64, Bdim * Hdim);
        flash_mma<<<grid, 128>>>();
    }
    // 4) output projection: [4096,1024] @ [1024,1024]^T
    {
        dim3 grid(Edim / 128, MROWS / 128);
        sgemm_tf32<<<grid, 256>>>(p_ctx, w_out, out, MROWS, Edim, Edim);
    }
}